// round 14
// baseline (speedup 1.0000x reference)
#include <cuda_runtime.h>
#include <cuda_bf16.h>
#include <math.h>
#include <stdint.h>

#define HD 128
#define MAXN 100000
#define MAXE 600000
#define NCMAX 4

// ---------------- scratch globals ----------------
__device__ float g_stats[2 * HD];
__device__ __align__(16) float g_sc[HD];
__device__ __align__(16) float g_off[HD];
__device__ float g_bias2[HD];
__device__ float g_b1f[HD];
__device__ __nv_bfloat16 g_agg_hi[MAXN * HD];
__device__ __nv_bfloat16 g_agg_lo[MAXN * HD];
__device__ __nv_bfloat16 g_xhi[MAXN * HD];
__device__ __nv_bfloat16 g_xlo[MAXN * HD];
__device__ int g_deg[MAXN];          // zero at load; re-zeroed by fill_csr each call
__device__ int g_tmp[MAXN + 1024];
__device__ int g_part[128];
__device__ int g_rowptr[MAXN + 1];
__device__ int g_cursor[MAXN];
__device__ int2 g_cse[MAXE];         // packed (src, weight bits)
__device__ __nv_bfloat16 g_wtc[NCMAX * 2 * 2 * HD * HD];
__device__ __nv_bfloat16 g_wroot_s[2 * HD * HD];   // per-layer rescaled root (hi|lo)
__device__ __nv_bfloat16 g_wt1[2 * HD * 2 * HD];   // rescaled W1 (hi|lo)

// ---------------- tiling constants ----------------
// Swizzled tile: 128 rows x 128 bytes, addr = row*128 + ((c16 ^ (row&7))*16)
#define TILE 16384
#define BSLOT(i) ((uint32_t)(i) * TILE)
#define ASLOT(i) ((uint32_t)(4 + (i)) * TILE)
// Epilogue staging planes (reuse pipeline smem post-compute):
// hi plane @0, lo plane @34816 (128 rows x 272B pitch), stats @69632
#define EPPITCH 272
#define PLANE 34816
#define STATS_OFF 69632
#define CONV_SMEM (7 * TILE)            // 114688 -> 2 CTAs/SM
#define MLP_A 2560
#define MLP_SMEM (MLP_A + 4 * TILE)     // 68096

__device__ __forceinline__ float gelu_exact(float v) {
    return 0.5f * v * (1.0f + erff(v * 0.70710678118654752440f));
}
__device__ __forceinline__ uint32_t smem_u32(const void* p) {
    uint32_t a;
    asm("{ .reg .u64 t; cvta.to.shared.u64 t, %1; cvt.u32.u64 %0, t; }" : "=r"(a) : "l"(p));
    return a;
}
__device__ __forceinline__ uint32_t bfbits(__nv_bfloat16 h) {
    return (uint32_t)__bfloat16_as_ushort(h);
}
__device__ __forceinline__ uint32_t swzoff(int row, int c16) {
    return (uint32_t)(row * 128 + ((c16 ^ (row & 7)) * 16));
}
__device__ __forceinline__ void split2(float x, float y, uint32_t& hi, uint32_t& lo) {
    __nv_bfloat16 hx = __float2bfloat16(x), hy = __float2bfloat16(y);
    __nv_bfloat16 lx = __float2bfloat16(x - __bfloat162float(hx));
    __nv_bfloat16 ly = __float2bfloat16(y - __bfloat162float(hy));
    hi = bfbits(hx) | (bfbits(hy) << 16);
    lo = bfbits(lx) | (bfbits(ly) << 16);
}
__device__ __forceinline__ float2 recon2(uint32_t hb, uint32_t lb) {
    float2 h = __bfloat1622float2(*(__nv_bfloat162*)&hb);
    float2 l = __bfloat1622float2(*(__nv_bfloat162*)&lb);
    return make_float2(h.x + l.x, h.y + l.y);
}
__device__ __forceinline__ void ldmx4(uint32_t* r, uint32_t addr) {
    asm volatile("ldmatrix.sync.aligned.m8n8.x4.shared.b16 {%0,%1,%2,%3}, [%4];"
                 : "=r"(r[0]), "=r"(r[1]), "=r"(r[2]), "=r"(r[3]) : "r"(addr));
}
__device__ __forceinline__ void mma_bf16(float* c, const uint32_t* a, const uint32_t* b) {
    asm volatile(
        "mma.sync.aligned.m16n8k16.row.col.f32.bf16.bf16.f32 "
        "{%0,%1,%2,%3},{%4,%5,%6,%7},{%8,%9},{%0,%1,%2,%3};"
        : "+f"(c[0]), "+f"(c[1]), "+f"(c[2]), "+f"(c[3])
        : "r"(a[0]), "r"(a[1]), "r"(a[2]), "r"(a[3]), "r"(b[0]), "r"(b[1]));
}
__device__ __forceinline__ void cp16(uint32_t dst, const void* src, int sz) {
    asm volatile("cp.async.cg.shared.global [%0], [%1], 16, %2;"
                 :: "r"(dst), "l"(src), "r"(sz) : "memory");
}
__device__ __forceinline__ void cp_commit() {
    asm volatile("cp.async.commit_group;" ::: "memory");
}

// ---------------- mega prep: weight split + x split + deg hist + sc/off init
__global__ void mega_prep(const float4* __restrict__ x4, uint2* __restrict__ xhi,
                          uint2* __restrict__ xlo,
                          const float* __restrict__ rel_w,
                          const float* __restrict__ root_w,
                          const int* __restrict__ ei, int* __restrict__ deg,
                          int NC, int n32, int E) {
    int i = blockIdx.x * 256 + threadIdx.x;
    if (i < HD) { g_sc[i] = 1.0f; g_off[i] = 0.0f; }
    if (i < n32) {
        float4 v = x4[i];
        uint32_t h0, l0, h1, l1;
        split2(v.x, v.y, h0, l0);
        split2(v.z, v.w, h1, l1);
        xhi[i] = make_uint2(h0, h1);
        xlo[i] = make_uint2(l0, l1);
    }
    if (i < E) atomicAdd(&deg[ei[E + i]], 1);
    int convTotal = NC * 2 * HD * HD;
    if (i < convTotal) {
        int l = i / (2 * HD * HD);
        int rem = i % (2 * HD * HD);
        int m = rem / (HD * HD);
        int r = rem % (HD * HD);
        int k = r >> 7, nn = r & 127;
        const float* W = m ? root_w : rel_w;
        float v = W[(size_t)l * HD * HD + k * HD + nn];
        __nv_bfloat16 hi = __float2bfloat16(v);
        __nv_bfloat16 lo = __float2bfloat16(v - __bfloat162float(hi));
        size_t base = ((size_t)(l * 2 + m) * 2) * HD * HD;
        g_wtc[base + nn * HD + k] = hi;
        g_wtc[base + HD * HD + nn * HD + k] = lo;
    }
}

// ---------------- CSR scan ----------------
__global__ void scan1(const int* __restrict__ deg, int* __restrict__ tmp,
                      int* __restrict__ part, int n) {
    __shared__ int warpsum[8];
    int b = blockIdx.x, t = threadIdx.x;
    int base = b * 1024 + t * 4;
    int v0 = (base + 0 < n) ? deg[base + 0] : 0;
    int v1 = (base + 1 < n) ? deg[base + 1] : 0;
    int v2 = (base + 2 < n) ? deg[base + 2] : 0;
    int v3 = (base + 3 < n) ? deg[base + 3] : 0;
    int s0 = v0, s1 = s0 + v1, s2 = s1 + v2, s3 = s2 + v3;
    int tot = s3;
#pragma unroll
    for (int d = 1; d < 32; d <<= 1) {
        int u = __shfl_up_sync(0xFFFFFFFF, tot, d);
        if ((t & 31) >= d) tot += u;
    }
    if ((t & 31) == 31) warpsum[t >> 5] = tot;
    __syncthreads();
    if (t == 0) {
        int r = 0;
#pragma unroll
        for (int i = 0; i < 8; i++) { int x = warpsum[i]; warpsum[i] = r; r += x; }
        part[b] = r;
    }
    __syncthreads();
    int excl = warpsum[t >> 5] + (tot - s3);
    if (base + 0 <= n) tmp[base + 0] = excl;
    if (base + 1 <= n) tmp[base + 1] = excl + s0;
    if (base + 2 <= n) tmp[base + 2] = excl + s1;
    if (base + 3 <= n) tmp[base + 3] = excl + s2;
}
__global__ void scan3p(const int* __restrict__ tmp, const int* __restrict__ part,
                       int* __restrict__ rowptr, int* __restrict__ cursor,
                       int n, int E, int nb) {
    __shared__ int pref[128];
    int t = threadIdx.x;
    if (t == 0) {
        int r = 0;
        for (int j = 0; j < nb; j++) { pref[j] = r; r += part[j]; }
    }
    __syncthreads();
    int i = blockIdx.x * 256 + t;
    if (i < n) {
        int v = tmp[i] + pref[i >> 10];
        rowptr[i] = v;
        cursor[i] = v;
    }
    if (i == n) rowptr[n] = E;
}
__global__ void fill_csr(const int* __restrict__ ei, const float* __restrict__ ea,
                         int* __restrict__ cursor, int2* __restrict__ cse,
                         int* __restrict__ deg, int E, int n) {
    int e = blockIdx.x * 256 + threadIdx.x;
    if (e < n) deg[e] = 0;
    if (e >= E) return;
    int d = ei[E + e];
    int pos = atomicAdd(&cursor[d], 1);
    cse[pos] = make_int2(ei[e], __float_as_int(ea[e]));
}

// ---------------- per-layer BN fold (stats of conv l-1, bn params l-1) ------
__global__ void rescale(const float* __restrict__ stats,
                        const float* __restrict__ rootW,
                        const float* __restrict__ relB,
                        const float* __restrict__ bng,
                        const float* __restrict__ bnb, int n) {
    int i = blockIdx.x * 256 + threadIdx.x;  // grid 64 -> 16384
    float invN = 1.0f / (float)n;
    if (i < HD * HD) {
        int k = i >> 7, nn = i & 127;
        float m = stats[k] * invN;
        float var = fmaxf(stats[HD + k] * invN - m * m, 0.f);
        float sck = rsqrtf(var + 1e-5f) * bng[k];
        float v = rootW[(size_t)k * HD + nn] * sck;
        __nv_bfloat16 hi = __float2bfloat16(v);
        __nv_bfloat16 lo = __float2bfloat16(v - __bfloat162float(hi));
        g_wroot_s[nn * HD + k] = hi;
        g_wroot_s[HD * HD + nn * HD + k] = lo;
        if (nn == 0) { g_sc[k] = sck; g_off[k] = bnb[k] - m * sck; }
    }
    if (blockIdx.x == 0 && threadIdx.x < HD) {
        int c = threadIdx.x;
        float acc = relB[c];
        for (int k = 0; k < HD; k++) {
            float m = stats[k] * invN;
            float var = fmaxf(stats[HD + k] * invN - m * m, 0.f);
            float sck = rsqrtf(var + 1e-5f) * bng[k];
            float offk = bnb[k] - m * sck;
            acc += offk * rootW[(size_t)k * HD + c];
        }
        g_bias2[c] = acc;
    }
}
__global__ void rescale_mlp(const float* __restrict__ stats,
                            const float* __restrict__ w1,
                            const float* __restrict__ b1,
                            const float* __restrict__ bng,
                            const float* __restrict__ bnb, int n) {
    int i = blockIdx.x * 256 + threadIdx.x;  // grid 128 -> 32768
    float invN = 1.0f / (float)n;
    if (i < 2 * HD * HD) {
        int k = i >> 7, nn = i & 127;  // k 0..255
        int kc = k & 127;
        float m = stats[kc] * invN;
        float var = fmaxf(stats[HD + kc] * invN - m * m, 0.f);
        float sck = rsqrtf(var + 1e-5f) * bng[kc];
        float v = w1[(size_t)k * HD + nn] * sck;
        __nv_bfloat16 hi = __float2bfloat16(v);
        __nv_bfloat16 lo = __float2bfloat16(v - __bfloat162float(hi));
        g_wt1[(size_t)nn * 256 + k] = hi;
        g_wt1[(size_t)HD * 2 * HD + nn * 256 + k] = lo;
    }
    if (blockIdx.x == 0 && threadIdx.x < HD) {
        int c = threadIdx.x;
        float acc = b1[c];
        for (int k = 0; k < 2 * HD; k++) {
            int kc = k & 127;
            float m = stats[kc] * invN;
            float var = fmaxf(stats[HD + kc] * invN - m * m, 0.f);
            float sck = rsqrtf(var + 1e-5f) * bng[kc];
            float offk = bnb[kc] - m * sck;
            acc += offk * w1[(size_t)k * HD + c];
        }
        g_b1f[c] = acc;
    }
}

// ---------------- CSR aggregation: in-flight BN, unrolled x2 ----------------
__global__ void agg_kernel(const uint2* __restrict__ xhi, const uint2* __restrict__ xlo,
                           const int* __restrict__ rowptr,
                           const int2* __restrict__ cse,
                           uint2* __restrict__ ahi, uint2* __restrict__ alo,
                           float* __restrict__ stats, int nn) {
    if (blockIdx.x == 0 && threadIdx.x < 2 * HD) stats[threadIdx.x] = 0.f;
    int node = (blockIdx.x * blockDim.x + threadIdx.x) >> 5;
    int lane = threadIdx.x & 31;
    if (node >= nn) return;
    float4 sc = *(const float4*)&g_sc[lane * 4];
    float4 of = *(const float4*)&g_off[lane * 4];
    int beg = rowptr[node], end = rowptr[node + 1];
    float4 acc = make_float4(0.f, 0.f, 0.f, 0.f);
    int e = beg;
    for (; e + 2 <= end; e += 2) {
        int2 p0 = __ldg(&cse[e]);
        int2 p1 = __ldg(&cse[e + 1]);
        uint2 vh0 = __ldg(&xhi[(size_t)p0.x * 32 + lane]);
        uint2 vl0 = __ldg(&xlo[(size_t)p0.x * 32 + lane]);
        uint2 vh1 = __ldg(&xhi[(size_t)p1.x * 32 + lane]);
        uint2 vl1 = __ldg(&xlo[(size_t)p1.x * 32 + lane]);
        float w0 = __int_as_float(p0.y), w1 = __int_as_float(p1.y);
        float2 a01 = recon2(vh0.x, vl0.x), a23 = recon2(vh0.y, vl0.y);
        float2 b01 = recon2(vh1.x, vl1.x), b23 = recon2(vh1.y, vl1.y);
        acc.x += (a01.x * sc.x + of.x) * w0 + (b01.x * sc.x + of.x) * w1;
        acc.y += (a01.y * sc.y + of.y) * w0 + (b01.y * sc.y + of.y) * w1;
        acc.z += (a23.x * sc.z + of.z) * w0 + (b23.x * sc.z + of.z) * w1;
        acc.w += (a23.y * sc.w + of.w) * w0 + (b23.y * sc.w + of.w) * w1;
    }
    if (e < end) {
        int2 p0 = __ldg(&cse[e]);
        uint2 vh0 = __ldg(&xhi[(size_t)p0.x * 32 + lane]);
        uint2 vl0 = __ldg(&xlo[(size_t)p0.x * 32 + lane]);
        float w0 = __int_as_float(p0.y);
        float2 a01 = recon2(vh0.x, vl0.x), a23 = recon2(vh0.y, vl0.y);
        acc.x += (a01.x * sc.x + of.x) * w0;
        acc.y += (a01.y * sc.y + of.y) * w0;
        acc.z += (a23.x * sc.z + of.z) * w0;
        acc.w += (a23.y * sc.w + of.w) * w0;
    }
    uint32_t h0, l0, h1, l1;
    split2(acc.x, acc.y, h0, l0);
    split2(acc.z, acc.w, h1, l1);
    ahi[(size_t)node * 32 + lane] = make_uint2(h0, h1);
    alo[(size_t)node * 32 + lane] = make_uint2(l0, l1);
}

// ---------------- conv GEMM: dedup schedule, split-output epilogue ----------
__device__ __forceinline__ void conv_issue_g(
    int g, int row0, int n, uint32_t sm, int t,
    const char* Ah0, const char* Al0, const char* Ah1, const char* Al1,
    const char* Wrh, const char* Wrl, const char* Woh, const char* Wol) {
    const signed char gAsrc[12] = {0, -1, 1, 0, -1, 1, 2, -1, 3, 2, -1, 3};
    const signed char gAkc [12] = {0,  0, 0, 1,  0, 1, 0,  0, 0, 1,  0, 1};
    const signed char gAslt[12] = {0,  0, 1, 2,  0, 0, 1,  0, 2, 0,  0, 1};
    const signed char gBsrc[12] = {0,  1, 0, 1, -1, 2, 3, -1, 2, 3, -1, -1};
    const signed char gBkc [12] = {0,  0, 1, 1,  0, 0, 0,  0, 1, 1,  0, 0};
    const signed char gBslt[12] = {0,  2, 1, 3,  0, 0, 2,  0, 1, 3,  0, 0};
    int as = gAsrc[g];
    if (as >= 0) {
        const char* A = (as == 0) ? Ah0 : (as == 1) ? Al0 : (as == 2) ? Ah1 : Al1;
        int kc = gAkc[g];
        uint32_t buf = sm + ASLOT(gAslt[g]);
#pragma unroll
        for (int p = 0; p < 4; p++) {
            int idx = p * 256 + t;
            int r = idx >> 3, u = idx & 7;
            int gr = row0 + r;
            cp16(buf + swzoff(r, u), A + (size_t)gr * 256 + kc * 128 + u * 16,
                 (gr < n) ? 16 : 0);
        }
    }
    int bs = gBsrc[g];
    if (bs >= 0) {
        const char* B = (bs == 0) ? Wrh : (bs == 1) ? Wrl : (bs == 2) ? Woh : Wol;
        int kc = gBkc[g];
        uint32_t buf = sm + BSLOT(gBslt[g]);
#pragma unroll
        for (int p = 0; p < 4; p++) {
            int idx = p * 256 + t;
            int r = idx >> 3, u = idx & 7;
            cp16(buf + swzoff(r, u), B + (size_t)r * 256 + kc * 128 + u * 16, 16);
        }
    }
}

__global__ void __launch_bounds__(256, 2) conv_mma(
    const char* __restrict__ Ah0, const char* __restrict__ Al0,
    const char* Ah1, const char* Al1,
    const char* __restrict__ Wrh, const char* __restrict__ Wrl,
    const char* __restrict__ Woh, const char* __restrict__ Wol,
    const float* __restrict__ bias,
    uint4* OutHi, uint4* OutLo,
    float* __restrict__ stats, int n) {
    extern __shared__ __align__(16) char smp[];
    uint32_t sm = smem_u32(smp);
    int t = threadIdx.x, wid = t >> 5, lane = t & 31;
    int row0 = blockIdx.x * 128;
    int mbase = (wid & 1) * 64, nbase = (wid >> 1) * 32;

    float c[4][4][4];
#pragma unroll
    for (int i = 0; i < 4; i++)
#pragma unroll
        for (int j = 0; j < 4; j++)
#pragma unroll
            for (int q = 0; q < 4; q++) c[i][j][q] = 0.f;

    int sub = lane >> 3, r8 = lane & 7;
    int rowA = mbase + r8 + ((sub & 1) << 3);
    int rowB = nbase + ((sub >> 1) << 3) + r8;
    int cA0 = sub >> 1, cB0 = sub & 1;

    const signed char sAslt[12] = {0, 0, 1, 2, 2, 0, 1, 1, 2, 0, 0, 1};
    const signed char sBslt[12] = {0, 2, 0, 1, 3, 1, 0, 2, 0, 1, 3, 1};

    conv_issue_g(0, row0, n, sm, t, Ah0, Al0, Ah1, Al1, Wrh, Wrl, Woh, Wol);
    cp_commit();
    conv_issue_g(1, row0, n, sm, t, Ah0, Al0, Ah1, Al1, Wrh, Wrl, Woh, Wol);
    cp_commit();
#pragma unroll
    for (int s = 0; s < 12; s++) {
        if (s < 11) {
            asm volatile("cp.async.wait_group 1;" ::: "memory");
        } else {
            asm volatile("cp.async.wait_group 0;" ::: "memory");
        }
        __syncthreads();
        if (s < 10) {
            conv_issue_g(s + 2, row0, n, sm, t, Ah0, Al0, Ah1, Al1, Wrh, Wrl, Woh, Wol);
            cp_commit();
        }
        uint32_t bufA = sm + ASLOT(sAslt[s]);
        uint32_t bufB = sm + BSLOT(sBslt[s]);
#pragma unroll
        for (int ks = 0; ks < 4; ks++) {
            int cA = ((cA0 + 2 * ks) ^ r8) * 16;
            int cB = ((cB0 + 2 * ks) ^ r8) * 16;
            uint32_t a[4][4], b[8];
#pragma unroll
            for (int mt = 0; mt < 4; mt++)
                ldmx4(a[mt], bufA + (uint32_t)((rowA + mt * 16) * 128 + cA));
#pragma unroll
            for (int bp = 0; bp < 2; bp++)
                ldmx4(b + bp * 4, bufB + (uint32_t)((rowB + bp * 16) * 128 + cB));
#pragma unroll
            for (int mt = 0; mt < 4; mt++)
#pragma unroll
                for (int nt = 0; nt < 4; nt++) mma_bf16(c[mt][nt], a[mt], b + nt * 2);
        }
    }
    __syncthreads();

    // Epilogue: +bias, gelu, split -> smem planes, fused BN stats
    if (t < 128) {
        *(float*)(smp + STATS_OFF + t * 4) = 0.f;
        *(float*)(smp + STATS_OFF + 512 + t * 4) = 0.f;
    }
    __syncthreads();
    int g = lane >> 2, tq = lane & 3;
    float bv[8];
#pragma unroll
    for (int nt = 0; nt < 4; nt++) {
        bv[nt * 2 + 0] = __ldg(&bias[nbase + nt * 8 + tq * 2 + 0]);
        bv[nt * 2 + 1] = __ldg(&bias[nbase + nt * 8 + tq * 2 + 1]);
    }
    float colsum[8], colsq[8];
#pragma unroll
    for (int j = 0; j < 8; j++) { colsum[j] = 0.f; colsq[j] = 0.f; }
#pragma unroll
    for (int mt = 0; mt < 4; mt++) {
        int lr0 = mbase + mt * 16 + g, lr1 = lr0 + 8;
        int gr0 = row0 + lr0, gr1 = row0 + lr1;
#pragma unroll
        for (int nt = 0; nt < 4; nt++) {
            int cb = nbase + nt * 8 + tq * 2;
            if (gr0 < n) {
                float o0 = gelu_exact(c[mt][nt][0] + bv[nt * 2]);
                float o1 = gelu_exact(c[mt][nt][1] + bv[nt * 2 + 1]);
                uint32_t hh, ll;
                split2(o0, o1, hh, ll);
                *(uint32_t*)(smp + lr0 * EPPITCH + cb * 2) = hh;
                *(uint32_t*)(smp + PLANE + lr0 * EPPITCH + cb * 2) = ll;
                colsum[nt * 2] += o0; colsq[nt * 2] += o0 * o0;
                colsum[nt * 2 + 1] += o1; colsq[nt * 2 + 1] += o1 * o1;
            }
            if (gr1 < n) {
                float o2 = gelu_exact(c[mt][nt][2] + bv[nt * 2]);
                float o3 = gelu_exact(c[mt][nt][3] + bv[nt * 2 + 1]);
                uint32_t hh, ll;
                split2(o2, o3, hh, ll);
                *(uint32_t*)(smp + lr1 * EPPITCH + cb * 2) = hh;
                *(uint32_t*)(smp + PLANE + lr1 * EPPITCH + cb * 2) = ll;
                colsum[nt * 2] += o2; colsq[nt * 2] += o2 * o2;
                colsum[nt * 2 + 1] += o3; colsq[nt * 2 + 1] += o3 * o3;
            }
        }
    }
#pragma unroll
    for (int j = 0; j < 8; j++) {
        float v = colsum[j], w = colsq[j];
        v += __shfl_down_sync(0xFFFFFFFF, v, 16); w += __shfl_down_sync(0xFFFFFFFF, w, 16);
        v += __shfl_down_sync(0xFFFFFFFF, v, 8);  w += __shfl_down_sync(0xFFFFFFFF, w, 8);
        v += __shfl_down_sync(0xFFFFFFFF, v, 4);  w += __shfl_down_sync(0xFFFFFFFF, w, 4);
        if (lane < 4) {
            int cb = nbase + (j >> 1) * 8 + lane * 2 + (j & 1);
            atomicAdd((float*)(smp + STATS_OFF + cb * 4), v);
            atomicAdd((float*)(smp + STATS_OFF + 512 + cb * 4), w);
        }
    }
    __syncthreads();
    if (t < 128) {
        atomicAdd(&stats[t], *(float*)(smp + STATS_OFF + t * 4));
        atomicAdd(&stats[HD + t], *(float*)(smp + STATS_OFF + 512 + t * 4));
    }
    // Coalesced split store: planes -> global (16B per thread per iter)
#pragma unroll
    for (int pl = 0; pl < 2; pl++) {
        uint4* gout = pl ? OutLo : OutHi;
        uint32_t base = pl * PLANE;
#pragma unroll
        for (int it = 0; it < 8; it++) {
            int idx = it * 256 + t;
            int r = idx >> 4, q = idx & 15;
            if (row0 + r < n) {
                uint4 v = *(uint4*)(smp + base + r * EPPITCH + q * 16);
                gout[(size_t)(row0 + r) * 16 + q] = v;
            }
        }
    }
}

// ---------------- edge MLP (HMMA; BN folded into W1/b1) ----------------
__global__ void __launch_bounds__(256, 2) mlp_mma(
    const char* __restrict__ Xhi, const char* __restrict__ Xlo,
    const int* __restrict__ eli,
    const __nv_bfloat16* __restrict__ W1h, const __nv_bfloat16* __restrict__ W1l,
    const float* __restrict__ B1, const float* __restrict__ W2,
    const float* __restrict__ B2, float* __restrict__ out, int EQ) {
    extern __shared__ __align__(16) char smp[];
    uint32_t sm = smem_u32(smp);
    int t = threadIdx.x, wid = t >> 5, lane = t & 31;
    int row0 = blockIdx.x * 128;
    int mbase = (wid & 1) * 64, nbase = (wid >> 1) * 32;

    if (t < HD) {
        *(float*)(smp + t * 4) = B1[t];
        *(float*)(smp + 512 + t * 4) = W2[t];
        *(float*)(smp + 1024 + t * 4) = 0.f;
        int gr = row0 + t;
        int e = (gr < EQ) ? gr : 0;
        *(int*)(smp + 1536 + t * 4) = eli[e];
        *(int*)(smp + 2048 + t * 4) = eli[EQ + e];
    }

    float c[4][4][4];
#pragma unroll
    for (int i = 0; i < 4; i++)
#pragma unroll
        for (int j = 0; j < 4; j++)
#pragma unroll
            for (int q = 0; q < 4; q++) c[i][j][q] = 0.f;

    int sub = lane >> 3, r8 = lane & 7;
    int rowA = mbase + r8 + ((sub & 1) << 3);
    int rowB = nbase + ((sub >> 1) << 3) + r8;
    int cA0 = sub >> 1, cB0 = sub & 1;

    for (int ch = 0; ch < 4; ch++) {
        int idxOff = (ch < 2) ? 1536 : 2048;
        int kc = ch & 1;
        __syncthreads();
#pragma unroll
        for (int p = 0; p < 4; p++) {
            int idx = p * 256 + t;
            int r = idx >> 3, u = idx & 7;
            int node = *(const int*)(smp + idxOff + r * 4);
            uint32_t o = swzoff(r, u);
            uint4 vh = *(const uint4*)(Xhi + (size_t)node * 256 + kc * 128 + u * 16);
            uint4 vl = *(const uint4*)(Xlo + (size_t)node * 256 + kc * 128 + u * 16);
            *(uint4*)(smp + MLP_A + o) = vh;
            *(uint4*)(smp + MLP_A + TILE + o) = vl;
        }
#pragma unroll
        for (int p = 0; p < 4; p++) {
            int lin = p * 256 + t;
            int nn = lin >> 3, q = lin & 7;
            uint32_t o = swzoff(nn, q);
            *(uint4*)(smp + MLP_A + 2 * TILE + o) =
                *(const uint4*)(W1h + (size_t)nn * 256 + ch * 64 + q * 8);
            *(uint4*)(smp + MLP_A + 3 * TILE + o) =
                *(const uint4*)(W1l + (size_t)nn * 256 + ch * 64 + q * 8);
        }
        __syncthreads();
#pragma unroll
        for (int ps = 0; ps < 3; ps++) {
            uint32_t Ab = sm + MLP_A + ((ps == 1) ? TILE : 0);
            uint32_t Bb = sm + MLP_A + 2 * TILE + ((ps == 2) ? TILE : 0);
#pragma unroll
            for (int ks = 0; ks < 4; ks++) {
                int cA = ((cA0 + 2 * ks) ^ r8) * 16;
                int cB = ((cB0 + 2 * ks) ^ r8) * 16;
                uint32_t a[4][4], b[8];
#pragma unroll
                for (int mt = 0; mt < 4; mt++)
                    ldmx4(a[mt], Ab + (uint32_t)((rowA + mt * 16) * 128 + cA));
#pragma unroll
                for (int bp = 0; bp < 2; bp++)
                    ldmx4(b + bp * 4, Bb + (uint32_t)((rowB + bp * 16) * 128 + cB));
#pragma unroll
                for (int mt = 0; mt < 4; mt++)
#pragma unroll
                    for (int nt = 0; nt < 4; nt++) mma_bf16(c[mt][nt], a[mt], b + nt * 2);
            }
        }
    }

    int g = lane >> 2, tq = lane & 3;
#pragma unroll
    for (int mt = 0; mt < 4; mt++) {
        float p0 = 0.f, p1 = 0.f;
#pragma unroll
        for (int nt = 0; nt < 4; nt++) {
            int cb = nbase + nt * 8 + tq * 2;
            float2 bvv = *(float2*)(smp + cb * 4);
            float2 wv = *(float2*)(smp + 512 + cb * 4);
            p0 += gelu_exact(c[mt][nt][0] + bvv.x) * wv.x
                + gelu_exact(c[mt][nt][1] + bvv.y) * wv.y;
            p1 += gelu_exact(c[mt][nt][2] + bvv.x) * wv.x
                + gelu_exact(c[mt][nt][3] + bvv.y) * wv.y;
        }
        p0 += __shfl_xor_sync(0xFFFFFFFF, p0, 1);
        p0 += __shfl_xor_sync(0xFFFFFFFF, p0, 2);
        p1 += __shfl_xor_sync(0xFFFFFFFF, p1, 1);
        p1 += __shfl_xor_sync(0xFFFFFFFF, p1, 2);
        if (tq == 0) {
            int lr = mbase + mt * 16 + g;
            atomicAdd((float*)(smp + 1024 + lr * 4), p0);
            atomicAdd((float*)(smp + 1024 + (lr + 8) * 4), p1);
        }
    }
    __syncthreads();
    if (t < 128) {
        int gr = row0 + t;
        if (gr < EQ) {
            float z = *(float*)(smp + 1024 + t * 4) + B2[0];
            out[gr] = 1.0f / (1.0f + expf(-z));
        }
    }
}

// ---------------------------------------------------------------------------
extern "C" void kernel_launch(void* const* d_in, const int* in_sizes, int n_in,
                              void* d_out, int out_size) {
    const float* x      = (const float*)d_in[0];
    const int*   ei     = (const int*)d_in[1];
    const float* ea     = (const float*)d_in[2];
    const int*   eli    = (const int*)d_in[3];
    const float* rel_w  = (const float*)d_in[4];
    const float* rel_b  = (const float*)d_in[5];
    const float* root_w = (const float*)d_in[6];
    const float* bn_g   = (const float*)d_in[7];
    const float* bn_b   = (const float*)d_in[8];
    const float* w1     = (const float*)d_in[9];
    const float* b1     = (const float*)d_in[10];
    const float* w2     = (const float*)d_in[11];
    const float* b2     = (const float*)d_in[12];

    int N  = in_sizes[0] / HD;
    int E  = in_sizes[1] / 2;
    int EQ = in_sizes[3] / 2;
    int NC = in_sizes[4] / (HD * HD);

    float *stats, *bias2, *b1f;
    __nv_bfloat16 *ahi, *alo, *xhi, *xlo, *wtc, *wt1, *wroot;
    int *deg, *tmp, *part, *rowptr, *cursor;
    int2 *cse;
    cudaGetSymbolAddress((void**)&stats,  g_stats);
    cudaGetSymbolAddress((void**)&bias2,  g_bias2);
    cudaGetSymbolAddress((void**)&b1f,    g_b1f);
    cudaGetSymbolAddress((void**)&ahi,    g_agg_hi);
    cudaGetSymbolAddress((void**)&alo,    g_agg_lo);
    cudaGetSymbolAddress((void**)&xhi,    g_xhi);
    cudaGetSymbolAddress((void**)&xlo,    g_xlo);
    cudaGetSymbolAddress((void**)&deg,    g_deg);
    cudaGetSymbolAddress((void**)&tmp,    g_tmp);
    cudaGetSymbolAddress((void**)&part,   g_part);
    cudaGetSymbolAddress((void**)&rowptr, g_rowptr);
    cudaGetSymbolAddress((void**)&cursor, g_cursor);
    cudaGetSymbolAddress((void**)&cse,    g_cse);
    cudaGetSymbolAddress((void**)&wtc,    g_wtc);
    cudaGetSymbolAddress((void**)&wt1,    g_wt1);
    cudaGetSymbolAddress((void**)&wroot,  g_wroot_s);

    cudaFuncSetAttribute(conv_mma, cudaFuncAttributeMaxDynamicSharedMemorySize, CONV_SMEM);
    cudaFuncSetAttribute(mlp_mma,  cudaFuncAttributeMaxDynamicSharedMemorySize, MLP_SMEM);

    int n32 = N * 32;
    int NB = (N + 1023) / 1024;
    int gb = (N + 127) / 128;
    int mb = (EQ + 127) / 128;

    mega_prep<<<(n32 + 255) / 256, 256>>>((const float4*)x, (uint2*)xhi, (uint2*)xlo,
                                          rel_w, root_w, ei, deg, NC, n32, E);
    scan1<<<NB, 256>>>(deg, tmp, part, N);
    scan3p<<<(N + 256) / 256, 256>>>(tmp, part, rowptr, cursor, N, E, NB);
    fill_csr<<<(E + 255) / 256, 256>>>(ei, ea, cursor, cse, deg, E, N);

    for (int l = 0; l < NC; l++) {
        if (l > 0) {
            rescale<<<64, 256>>>(stats, root_w + (size_t)l * HD * HD,
                                 rel_b + (size_t)l * HD,
                                 bn_g + (size_t)(l - 1) * HD,
                                 bn_b + (size_t)(l - 1) * HD, N);
        }
        agg_kernel<<<(N + 7) / 8, 256>>>((const uint2*)xhi, (const uint2*)xlo,
                                         rowptr, cse,
                                         (uint2*)ahi, (uint2*)alo, stats, N);
        size_t wb = (size_t)(l * 2) * 2 * HD * HD;
        const char* Woh = (l == 0) ? (const char*)(wtc + wb + 2 * HD * HD)
                                   : (const char*)wroot;
        const char* Wol = (l == 0) ? (const char*)(wtc + wb + 3 * HD * HD)
                                   : (const char*)(wroot + HD * HD);
        const float* biasp = (l == 0) ? (rel_b + (size_t)l * HD) : bias2;
        conv_mma<<<gb, 256, CONV_SMEM>>>(
            (const char*)ahi, (const char*)alo, (const char*)xhi, (const char*)xlo,
            (const char*)(wtc + wb), (const char*)(wtc + wb + HD * HD),
            Woh, Wol, biasp,
            (uint4*)xhi, (uint4*)xlo, stats, N);
    }
    rescale_mlp<<<128, 256>>>(stats, w1, b1,
                              bn_g + (size_t)(NC - 1) * HD,
                              bn_b + (size_t)(NC - 1) * HD, N);
    mlp_mma<<<mb, 256, MLP_SMEM>>>((const char*)xhi, (const char*)xlo, eli,
                                   wt1, wt1 + (size_t)HD * 2 * HD,
                                   b1f, w2, b2, (float*)d_out, EQ);
}

// round 15
// speedup vs baseline: 1.1358x; 1.1358x over previous
#include <cuda_runtime.h>
#include <cuda_bf16.h>
#include <math.h>
#include <stdint.h>

#define HD 128
#define MAXN 100000
#define MAXE 600000
#define NCMAX 4

// ---------------- scratch globals ----------------
__device__ float g_h[MAXN * HD];
__device__ float g_stats[2 * HD];
__device__ __nv_bfloat16 g_agg_hi[MAXN * HD];
__device__ __nv_bfloat16 g_agg_lo[MAXN * HD];
__device__ __nv_bfloat16 g_xhi[MAXN * HD];
__device__ __nv_bfloat16 g_xlo[MAXN * HD];
__device__ int g_deg[MAXN];          // zero at load; re-zeroed by fill_csr each call
__device__ int g_tmp[MAXN + 1024];
__device__ int g_part[128];
__device__ int g_rowptr[MAXN + 1];
__device__ int g_cursor[MAXN];
__device__ int2 g_cse[MAXE];         // packed (src, weight bits)
__device__ __nv_bfloat16 g_wtc[NCMAX * 2 * 2 * HD * HD];
__device__ __nv_bfloat16 g_wt1[2 * HD * 2 * HD];

// ---------------- tiling constants ----------------
// Swizzled tile: 128 rows x 128 bytes, addr = row*128 + ((c16 ^ (row&7))*16)
#define TILE 16384
// conv smem: 4 B slots (rel->root overwrite) + 3-slot A ring; stats reuse B0.
#define BSLOT(i) ((uint32_t)(i) * TILE)
#define ASLOT(i) ((uint32_t)(4 + (i)) * TILE)
#define STATS_OFF 0
#define CONV_SMEM (7 * TILE)            // 114688 -> 2 CTAs/SM
#define MLP_A 2560
#define MLP_SMEM (MLP_A + 4 * TILE)     // 68096

__device__ __forceinline__ float gelu_exact(float v) {
    return 0.5f * v * (1.0f + erff(v * 0.70710678118654752440f));
}
__device__ __forceinline__ uint32_t smem_u32(const void* p) {
    uint32_t a;
    asm("{ .reg .u64 t; cvta.to.shared.u64 t, %1; cvt.u32.u64 %0, t; }" : "=r"(a) : "l"(p));
    return a;
}
__device__ __forceinline__ uint32_t bfbits(__nv_bfloat16 h) {
    return (uint32_t)__bfloat16_as_ushort(h);
}
__device__ __forceinline__ uint32_t swzoff(int row, int c16) {
    return (uint32_t)(row * 128 + ((c16 ^ (row & 7)) * 16));
}
__device__ __forceinline__ void split2(float x, float y, uint32_t& hi, uint32_t& lo) {
    __nv_bfloat16 hx = __float2bfloat16(x), hy = __float2bfloat16(y);
    __nv_bfloat16 lx = __float2bfloat16(x - __bfloat162float(hx));
    __nv_bfloat16 ly = __float2bfloat16(y - __bfloat162float(hy));
    hi = bfbits(hx) | (bfbits(hy) << 16);
    lo = bfbits(lx) | (bfbits(ly) << 16);
}
__device__ __forceinline__ float2 recon2(uint32_t hb, uint32_t lb) {
    float2 h = __bfloat1622float2(*(__nv_bfloat162*)&hb);
    float2 l = __bfloat1622float2(*(__nv_bfloat162*)&lb);
    return make_float2(h.x + l.x, h.y + l.y);
}
__device__ __forceinline__ void ldmx4(uint32_t* r, uint32_t addr) {
    asm volatile("ldmatrix.sync.aligned.m8n8.x4.shared.b16 {%0,%1,%2,%3}, [%4];"
                 : "=r"(r[0]), "=r"(r[1]), "=r"(r[2]), "=r"(r[3]) : "r"(addr));
}
__device__ __forceinline__ void mma_bf16(float* c, const uint32_t* a, const uint32_t* b) {
    asm volatile(
        "mma.sync.aligned.m16n8k16.row.col.f32.bf16.bf16.f32 "
        "{%0,%1,%2,%3},{%4,%5,%6,%7},{%8,%9},{%0,%1,%2,%3};"
        : "+f"(c[0]), "+f"(c[1]), "+f"(c[2]), "+f"(c[3])
        : "r"(a[0]), "r"(a[1]), "r"(a[2]), "r"(a[3]), "r"(b[0]), "r"(b[1]));
}
__device__ __forceinline__ void cp16(uint32_t dst, const void* src, int sz) {
    asm volatile("cp.async.cg.shared.global [%0], [%1], 16, %2;"
                 :: "r"(dst), "l"(src), "r"(sz) : "memory");
}
__device__ __forceinline__ void cp_commit() {
    asm volatile("cp.async.commit_group;" ::: "memory");
}

// ---------------- mega prep: weight split + x split + degree histogram ------
__global__ void mega_prep(const float4* __restrict__ x4, uint2* __restrict__ xhi,
                          uint2* __restrict__ xlo,
                          const float* __restrict__ rel_w,
                          const float* __restrict__ root_w,
                          const float* __restrict__ w1,
                          const int* __restrict__ ei, int* __restrict__ deg,
                          int NC, int n32, int E) {
    int i = blockIdx.x * 256 + threadIdx.x;
    if (i < n32) {
        float4 v = x4[i];
        uint32_t h0, l0, h1, l1;
        split2(v.x, v.y, h0, l0);
        split2(v.z, v.w, h1, l1);
        xhi[i] = make_uint2(h0, h1);
        xlo[i] = make_uint2(l0, l1);
    }
    if (i < E) atomicAdd(&deg[ei[E + i]], 1);
    int convTotal = NC * 2 * HD * HD;
    if (i < convTotal) {
        int l = i / (2 * HD * HD);
        int rem = i % (2 * HD * HD);
        int m = rem / (HD * HD);
        int r = rem % (HD * HD);
        int k = r >> 7, nn = r & 127;
        const float* W = m ? root_w : rel_w;
        float v = W[(size_t)l * HD * HD + k * HD + nn];
        __nv_bfloat16 hi = __float2bfloat16(v);
        __nv_bfloat16 lo = __float2bfloat16(v - __bfloat162float(hi));
        size_t base = ((size_t)(l * 2 + m) * 2) * HD * HD;
        g_wtc[base + nn * HD + k] = hi;
        g_wtc[base + HD * HD + nn * HD + k] = lo;
    } else if (i < convTotal + 2 * HD * HD) {
        int r = i - convTotal;
        int k = r >> 7, nn = r & 127;
        float v = w1[(size_t)k * HD + nn];
        __nv_bfloat16 hi = __float2bfloat16(v);
        __nv_bfloat16 lo = __float2bfloat16(v - __bfloat162float(hi));
        g_wt1[(size_t)nn * 256 + k] = hi;
        g_wt1[(size_t)HD * 2 * HD + nn * 256 + k] = lo;
    }
}

// ---------------- CSR scan ----------------
__global__ void scan1(const int* __restrict__ deg, int* __restrict__ tmp,
                      int* __restrict__ part, int n) {
    __shared__ int warpsum[8];
    int b = blockIdx.x, t = threadIdx.x;
    int base = b * 1024 + t * 4;
    int v0 = (base + 0 < n) ? deg[base + 0] : 0;
    int v1 = (base + 1 < n) ? deg[base + 1] : 0;
    int v2 = (base + 2 < n) ? deg[base + 2] : 0;
    int v3 = (base + 3 < n) ? deg[base + 3] : 0;
    int s0 = v0, s1 = s0 + v1, s2 = s1 + v2, s3 = s2 + v3;
    int tot = s3;
#pragma unroll
    for (int d = 1; d < 32; d <<= 1) {
        int u = __shfl_up_sync(0xFFFFFFFF, tot, d);
        if ((t & 31) >= d) tot += u;
    }
    if ((t & 31) == 31) warpsum[t >> 5] = tot;
    __syncthreads();
    if (t == 0) {
        int r = 0;
#pragma unroll
        for (int i = 0; i < 8; i++) { int x = warpsum[i]; warpsum[i] = r; r += x; }
        part[b] = r;
    }
    __syncthreads();
    int excl = warpsum[t >> 5] + (tot - s3);
    if (base + 0 <= n) tmp[base + 0] = excl;
    if (base + 1 <= n) tmp[base + 1] = excl + s0;
    if (base + 2 <= n) tmp[base + 2] = excl + s1;
    if (base + 3 <= n) tmp[base + 3] = excl + s2;
}
__global__ void scan3p(const int* __restrict__ tmp, const int* __restrict__ part,
                       int* __restrict__ rowptr, int* __restrict__ cursor,
                       int n, int E, int nb) {
    __shared__ int pref[128];
    int t = threadIdx.x;
    if (t == 0) {
        int r = 0;
        for (int j = 0; j < nb; j++) { pref[j] = r; r += part[j]; }
    }
    __syncthreads();
    int i = blockIdx.x * 256 + t;
    if (i < n) {
        int v = tmp[i] + pref[i >> 10];
        rowptr[i] = v;
        cursor[i] = v;
    }
    if (i == n) rowptr[n] = E;
}
__global__ void fill_csr(const int* __restrict__ ei, const float* __restrict__ ea,
                         int* __restrict__ cursor, int2* __restrict__ cse,
                         int* __restrict__ deg, int E, int n) {
    int e = blockIdx.x * 256 + threadIdx.x;
    if (e < n) deg[e] = 0;
    if (e >= E) return;
    int d = ei[E + e];
    int pos = atomicAdd(&cursor[d], 1);
    cse[pos] = make_int2(ei[e], __float_as_int(ea[e]));
}

// ---------------- CSR aggregation: warp per node, unrolled x2 ---------------
__global__ void agg_kernel(const uint2* __restrict__ xhi, const uint2* __restrict__ xlo,
                           const int* __restrict__ rowptr,
                           const int2* __restrict__ cse,
                           uint2* __restrict__ ahi, uint2* __restrict__ alo,
                           float* __restrict__ stats, int nn) {
    if (blockIdx.x == 0 && threadIdx.x < 2 * HD) stats[threadIdx.x] = 0.f;
    int node = (blockIdx.x * blockDim.x + threadIdx.x) >> 5;
    int lane = threadIdx.x & 31;
    if (node >= nn) return;
    int beg = rowptr[node], end = rowptr[node + 1];
    float4 acc = make_float4(0.f, 0.f, 0.f, 0.f);
    int e = beg;
    for (; e + 2 <= end; e += 2) {
        int2 p0 = __ldg(&cse[e]);
        int2 p1 = __ldg(&cse[e + 1]);
        uint2 vh0 = __ldg(&xhi[(size_t)p0.x * 32 + lane]);
        uint2 vl0 = __ldg(&xlo[(size_t)p0.x * 32 + lane]);
        uint2 vh1 = __ldg(&xhi[(size_t)p1.x * 32 + lane]);
        uint2 vl1 = __ldg(&xlo[(size_t)p1.x * 32 + lane]);
        float w0 = __int_as_float(p0.y), w1 = __int_as_float(p1.y);
        float2 a01 = recon2(vh0.x, vl0.x), a23 = recon2(vh0.y, vl0.y);
        float2 b01 = recon2(vh1.x, vl1.x), b23 = recon2(vh1.y, vl1.y);
        acc.x += a01.x * w0 + b01.x * w1;
        acc.y += a01.y * w0 + b01.y * w1;
        acc.z += a23.x * w0 + b23.x * w1;
        acc.w += a23.y * w0 + b23.y * w1;
    }
    if (e < end) {
        int2 p0 = __ldg(&cse[e]);
        uint2 vh0 = __ldg(&xhi[(size_t)p0.x * 32 + lane]);
        uint2 vl0 = __ldg(&xlo[(size_t)p0.x * 32 + lane]);
        float w0 = __int_as_float(p0.y);
        float2 a01 = recon2(vh0.x, vl0.x), a23 = recon2(vh0.y, vl0.y);
        acc.x += a01.x * w0;
        acc.y += a01.y * w0;
        acc.z += a23.x * w0;
        acc.w += a23.y * w0;
    }
    uint32_t h0, l0, h1, l1;
    split2(acc.x, acc.y, h0, l0);
    split2(acc.z, acc.w, h1, l1);
    ahi[(size_t)node * 32 + lane] = make_uint2(h0, h1);
    alo[(size_t)node * 32 + lane] = make_uint2(l0, l1);
}

// ---------------- conv GEMM: dedup schedule, 4 B slots + 3 A ring -----------
__device__ __forceinline__ void conv_issue_g(
    int g, int row0, int n, uint32_t sm, int t,
    const char* Ah0, const char* Al0, const char* Ah1, const char* Al1,
    const char* Wrh, const char* Wrl, const char* Woh, const char* Wol) {
    const signed char gAsrc[12] = {0, -1, 1, 0, -1, 1, 2, -1, 3, 2, -1, 3};
    const signed char gAkc [12] = {0,  0, 0, 1,  0, 1, 0,  0, 0, 1,  0, 1};
    const signed char gAslt[12] = {0,  0, 1, 2,  0, 0, 1,  0, 2, 0,  0, 1};
    const signed char gBsrc[12] = {0,  1, 0, 1, -1, 2, 3, -1, 2, 3, -1, -1};
    const signed char gBkc [12] = {0,  0, 1, 1,  0, 0, 0,  0, 1, 1,  0, 0};
    const signed char gBslt[12] = {0,  2, 1, 3,  0, 0, 2,  0, 1, 3,  0, 0};
    int as = gAsrc[g];
    if (as >= 0) {
        const char* A = (as == 0) ? Ah0 : (as == 1) ? Al0 : (as == 2) ? Ah1 : Al1;
        int kc = gAkc[g];
        uint32_t buf = sm + ASLOT(gAslt[g]);
#pragma unroll
        for (int p = 0; p < 4; p++) {
            int idx = p * 256 + t;
            int r = idx >> 3, u = idx & 7;
            int gr = row0 + r;
            cp16(buf + swzoff(r, u), A + (size_t)gr * 256 + kc * 128 + u * 16,
                 (gr < n) ? 16 : 0);
        }
    }
    int bs = gBsrc[g];
    if (bs >= 0) {
        const char* B = (bs == 0) ? Wrh : (bs == 1) ? Wrl : (bs == 2) ? Woh : Wol;
        int kc = gBkc[g];
        uint32_t buf = sm + BSLOT(gBslt[g]);
#pragma unroll
        for (int p = 0; p < 4; p++) {
            int idx = p * 256 + t;
            int r = idx >> 3, u = idx & 7;
            cp16(buf + swzoff(r, u), B + (size_t)r * 256 + kc * 128 + u * 16, 16);
        }
    }
}

__global__ void __launch_bounds__(256, 2) conv_mma(
    const char* __restrict__ Ah0, const char* __restrict__ Al0,
    const char* __restrict__ Ah1, const char* __restrict__ Al1,
    const char* __restrict__ Wrh, const char* __restrict__ Wrl,
    const char* __restrict__ Woh, const char* __restrict__ Wol,
    const float* __restrict__ bias, float* __restrict__ Hout,
    float* __restrict__ stats, int n) {
    extern __shared__ __align__(16) char smp[];
    uint32_t sm = smem_u32(smp);
    int t = threadIdx.x, wid = t >> 5, lane = t & 31;
    int row0 = blockIdx.x * 128;
    int mbase = (wid & 1) * 64, nbase = (wid >> 1) * 32;

    float c[4][4][4];
#pragma unroll
    for (int i = 0; i < 4; i++)
#pragma unroll
        for (int j = 0; j < 4; j++)
#pragma unroll
            for (int q = 0; q < 4; q++) c[i][j][q] = 0.f;

    int sub = lane >> 3, r8 = lane & 7;
    int rowA = mbase + r8 + ((sub & 1) << 3);
    int rowB = nbase + ((sub >> 1) << 3) + r8;
    int cA0 = sub >> 1, cB0 = sub & 1;

    const signed char sAslt[12] = {0, 0, 1, 2, 2, 0, 1, 1, 2, 0, 0, 1};
    const signed char sBslt[12] = {0, 2, 0, 1, 3, 1, 0, 2, 0, 1, 3, 1};

    conv_issue_g(0, row0, n, sm, t, Ah0, Al0, Ah1, Al1, Wrh, Wrl, Woh, Wol);
    cp_commit();
    conv_issue_g(1, row0, n, sm, t, Ah0, Al0, Ah1, Al1, Wrh, Wrl, Woh, Wol);
    cp_commit();
#pragma unroll
    for (int s = 0; s < 12; s++) {
        if (s < 11) {
            asm volatile("cp.async.wait_group 1;" ::: "memory");
        } else {
            asm volatile("cp.async.wait_group 0;" ::: "memory");
        }
        __syncthreads();
        if (s < 10) {
            conv_issue_g(s + 2, row0, n, sm, t, Ah0, Al0, Ah1, Al1, Wrh, Wrl, Woh, Wol);
            cp_commit();  // empty groups keep the wait_group count aligned
        }
        uint32_t bufA = sm + ASLOT(sAslt[s]);
        uint32_t bufB = sm + BSLOT(sBslt[s]);
#pragma unroll
        for (int ks = 0; ks < 4; ks++) {
            int cA = ((cA0 + 2 * ks) ^ r8) * 16;
            int cB = ((cB0 + 2 * ks) ^ r8) * 16;
            uint32_t a[4][4], b[8];
#pragma unroll
            for (int mt = 0; mt < 4; mt++)
                ldmx4(a[mt], bufA + (uint32_t)((rowA + mt * 16) * 128 + cA));
#pragma unroll
            for (int bp = 0; bp < 2; bp++)
                ldmx4(b + bp * 4, bufB + (uint32_t)((rowB + bp * 16) * 128 + cB));
#pragma unroll
            for (int mt = 0; mt < 4; mt++)
#pragma unroll
                for (int nt = 0; nt < 4; nt++) mma_bf16(c[mt][nt], a[mt], b + nt * 2);
        }
    }
    __syncthreads();

    // Epilogue: +bias, gelu, store, fused BN stats (stats reuse B slot 0)
    if (t < 128) {
        *(float*)(smp + STATS_OFF + t * 4) = 0.f;
        *(float*)(smp + STATS_OFF + 512 + t * 4) = 0.f;
    }
    __syncthreads();
    int g = lane >> 2, tq = lane & 3;
    float bv[8];
#pragma unroll
    for (int nt = 0; nt < 4; nt++) {
        bv[nt * 2 + 0] = __ldg(&bias[nbase + nt * 8 + tq * 2 + 0]);
        bv[nt * 2 + 1] = __ldg(&bias[nbase + nt * 8 + tq * 2 + 1]);
    }
    float colsum[8], colsq[8];
#pragma unroll
    for (int j = 0; j < 8; j++) { colsum[j] = 0.f; colsq[j] = 0.f; }
#pragma unroll
    for (int mt = 0; mt < 4; mt++) {
        int gr0 = row0 + mbase + mt * 16 + g, gr1 = gr0 + 8;
#pragma unroll
        for (int nt = 0; nt < 4; nt++) {
            int cb = nbase + nt * 8 + tq * 2;
            if (gr0 < n) {
                float o0 = gelu_exact(c[mt][nt][0] + bv[nt * 2]);
                float o1 = gelu_exact(c[mt][nt][1] + bv[nt * 2 + 1]);
                *(float2*)(Hout + (size_t)gr0 * HD + cb) = make_float2(o0, o1);
                colsum[nt * 2] += o0; colsq[nt * 2] += o0 * o0;
                colsum[nt * 2 + 1] += o1; colsq[nt * 2 + 1] += o1 * o1;
            }
            if (gr1 < n) {
                float o2 = gelu_exact(c[mt][nt][2] + bv[nt * 2]);
                float o3 = gelu_exact(c[mt][nt][3] + bv[nt * 2 + 1]);
                *(float2*)(Hout + (size_t)gr1 * HD + cb) = make_float2(o2, o3);
                colsum[nt * 2] += o2; colsq[nt * 2] += o2 * o2;
                colsum[nt * 2 + 1] += o3; colsq[nt * 2 + 1] += o3 * o3;
            }
        }
    }
#pragma unroll
    for (int j = 0; j < 8; j++) {
        float v = colsum[j], w = colsq[j];
        v += __shfl_down_sync(0xFFFFFFFF, v, 16); w += __shfl_down_sync(0xFFFFFFFF, w, 16);
        v += __shfl_down_sync(0xFFFFFFFF, v, 8);  w += __shfl_down_sync(0xFFFFFFFF, w, 8);
        v += __shfl_down_sync(0xFFFFFFFF, v, 4);  w += __shfl_down_sync(0xFFFFFFFF, w, 4);
        if (lane < 4) {
            int cb = nbase + (j >> 1) * 8 + lane * 2 + (j & 1);
            atomicAdd((float*)(smp + STATS_OFF + cb * 4), v);
            atomicAdd((float*)(smp + STATS_OFF + 512 + cb * 4), w);
        }
    }
    __syncthreads();
    if (t < 128) {
        atomicAdd(&stats[t], *(float*)(smp + STATS_OFF + t * 4));
        atomicAdd(&stats[HD + t], *(float*)(smp + STATS_OFF + 512 + t * 4));
    }
}

// ---------------- BN normalize -> emit split bf16 (2-row ILP) ---------------
__global__ void bn_kernel(const float4* __restrict__ h4, const float* __restrict__ stats,
                          const float* __restrict__ g, const float* __restrict__ b,
                          uint2* __restrict__ xhi, uint2* __restrict__ xlo, int n) {
    int total = n * 32;
    int half = (total + 1) >> 1;
    int i0 = blockIdx.x * blockDim.x + threadIdx.x;
    if (i0 >= half) return;
    int i1 = i0 + half;
    float invN = 1.0f / (float)n;

    // issue both loads before any compute (MLP=2)
    float4 h0v = h4[i0];
    float4 h1v = (i1 < total) ? h4[i1] : make_float4(0.f, 0.f, 0.f, 0.f);

#pragma unroll
    for (int pass = 0; pass < 2; pass++) {
        int i = pass ? i1 : i0;
        if (i >= total) break;
        float4 h = pass ? h1v : h0v;
        int c4 = i & 31;
        float4 s = ((const float4*)stats)[c4];
        float4 q = ((const float4*)stats)[32 + c4];
        float4 gg = ((const float4*)g)[c4];
        float4 bb = ((const float4*)b)[c4];
        float m0 = s.x * invN, m1 = s.y * invN, m2 = s.z * invN, m3 = s.w * invN;
        float sc0 = rsqrtf(fmaxf(q.x * invN - m0 * m0, 0.f) + 1e-5f) * gg.x;
        float sc1 = rsqrtf(fmaxf(q.y * invN - m1 * m1, 0.f) + 1e-5f) * gg.y;
        float sc2 = rsqrtf(fmaxf(q.z * invN - m2 * m2, 0.f) + 1e-5f) * gg.z;
        float sc3 = rsqrtf(fmaxf(q.w * invN - m3 * m3, 0.f) + 1e-5f) * gg.w;
        float ox = (h.x - m0) * sc0 + bb.x;
        float oy = (h.y - m1) * sc1 + bb.y;
        float oz = (h.z - m2) * sc2 + bb.z;
        float ow = (h.w - m3) * sc3 + bb.w;
        uint32_t h0, l0, h1, l1;
        split2(ox, oy, h0, l0);
        split2(oz, ow, h1, l1);
        xhi[i] = make_uint2(h0, h1);
        xlo[i] = make_uint2(l0, l1);
    }
}

// ---------------- edge MLP (HMMA, swizzled tiles) ----------------
__global__ void __launch_bounds__(256, 2) mlp_mma(
    const char* __restrict__ Xhi, const char* __restrict__ Xlo,
    const int* __restrict__ eli,
    const __nv_bfloat16* __restrict__ W1h, const __nv_bfloat16* __restrict__ W1l,
    const float* __restrict__ B1, const float* __restrict__ W2,
    const float* __restrict__ B2, float* __restrict__ out, int EQ) {
    extern __shared__ __align__(16) char smp[];
    uint32_t sm = smem_u32(smp);
    int t = threadIdx.x, wid = t >> 5, lane = t & 31;
    int row0 = blockIdx.x * 128;
    int mbase = (wid & 1) * 64, nbase = (wid >> 1) * 32;

    if (t < HD) {
        *(float*)(smp + t * 4) = B1[t];
        *(float*)(smp + 512 + t * 4) = W2[t];
        *(float*)(smp + 1024 + t * 4) = 0.f;
        int gr = row0 + t;
        int e = (gr < EQ) ? gr : 0;
        *(int*)(smp + 1536 + t * 4) = eli[e];
        *(int*)(smp + 2048 + t * 4) = eli[EQ + e];
    }

    float c[4][4][4];
#pragma unroll
    for (int i = 0; i < 4; i++)
#pragma unroll
        for (int j = 0; j < 4; j++)
#pragma unroll
            for (int q = 0; q < 4; q++) c[i][j][q] = 0.f;

    int sub = lane >> 3, r8 = lane & 7;
    int rowA = mbase + r8 + ((sub & 1) << 3);
    int rowB = nbase + ((sub >> 1) << 3) + r8;
    int cA0 = sub >> 1, cB0 = sub & 1;

    for (int ch = 0; ch < 4; ch++) {
        int idxOff = (ch < 2) ? 1536 : 2048;
        int kc = ch & 1;
        __syncthreads();
#pragma unroll
        for (int p = 0; p < 4; p++) {
            int idx = p * 256 + t;
            int r = idx >> 3, u = idx & 7;
            int node = *(const int*)(smp + idxOff + r * 4);
            uint32_t o = swzoff(r, u);
            uint4 vh = *(const uint4*)(Xhi + (size_t)node * 256 + kc * 128 + u * 16);
            uint4 vl = *(const uint4*)(Xlo + (size_t)node * 256 + kc * 128 + u * 16);
            *(uint4*)(smp + MLP_A + o) = vh;
            *(uint4*)(smp + MLP_A + TILE + o) = vl;
        }
#pragma unroll
        for (int p = 0; p < 4; p++) {
            int lin = p * 256 + t;
            int nn = lin >> 3, q = lin & 7;
            uint32_t o = swzoff(nn, q);
            *(uint4*)(smp + MLP_A + 2 * TILE + o) =
                *(const uint4*)(W1h + (size_t)nn * 256 + ch * 64 + q * 8);
            *(uint4*)(smp + MLP_A + 3 * TILE + o) =
                *(const uint4*)(W1l + (size_t)nn * 256 + ch * 64 + q * 8);
        }
        __syncthreads();
#pragma unroll
        for (int ps = 0; ps < 3; ps++) {
            uint32_t Ab = sm + MLP_A + ((ps == 1) ? TILE : 0);
            uint32_t Bb = sm + MLP_A + 2 * TILE + ((ps == 2) ? TILE : 0);
#pragma unroll
            for (int ks = 0; ks < 4; ks++) {
                int cA = ((cA0 + 2 * ks) ^ r8) * 16;
                int cB = ((cB0 + 2 * ks) ^ r8) * 16;
                uint32_t a[4][4], b[8];
#pragma unroll
                for (int mt = 0; mt < 4; mt++)
                    ldmx4(a[mt], Ab + (uint32_t)((rowA + mt * 16) * 128 + cA));
#pragma unroll
                for (int bp = 0; bp < 2; bp++)
                    ldmx4(b + bp * 4, Bb + (uint32_t)((rowB + bp * 16) * 128 + cB));
#pragma unroll
                for (int mt = 0; mt < 4; mt++)
#pragma unroll
                    for (int nt = 0; nt < 4; nt++) mma_bf16(c[mt][nt], a[mt], b + nt * 2);
            }
        }
    }

    int g = lane >> 2, tq = lane & 3;
#pragma unroll
    for (int mt = 0; mt < 4; mt++) {
        float p0 = 0.f, p1 = 0.f;
#pragma unroll
        for (int nt = 0; nt < 4; nt++) {
            int cb = nbase + nt * 8 + tq * 2;
            float2 bvv = *(float2*)(smp + cb * 4);
            float2 wv = *(float2*)(smp + 512 + cb * 4);
            p0 += gelu_exact(c[mt][nt][0] + bvv.x) * wv.x
                + gelu_exact(c[mt][nt][1] + bvv.y) * wv.y;
            p1 += gelu_exact(c[mt][nt][2] + bvv.x) * wv.x
                + gelu_exact(c[mt][nt][3] + bvv.y) * wv.y;
        }
        p0 += __shfl_xor_sync(0xFFFFFFFF, p0, 1);
        p0 += __shfl_xor_sync(0xFFFFFFFF, p0, 2);
        p1 += __shfl_xor_sync(0xFFFFFFFF, p1, 1);
        p1 += __shfl_xor_sync(0xFFFFFFFF, p1, 2);
        if (tq == 0) {
            int lr = mbase + mt * 16 + g;
            atomicAdd((float*)(smp + 1024 + lr * 4), p0);
            atomicAdd((float*)(smp + 1024 + (lr + 8) * 4), p1);
        }
    }
    __syncthreads();
    if (t < 128) {
        int gr = row0 + t;
        if (gr < EQ) {
            float z = *(float*)(smp + 1024 + t * 4) + B2[0];
            out[gr] = 1.0f / (1.0f + expf(-z));
        }
    }
}

// ---------------------------------------------------------------------------
extern "C" void kernel_launch(void* const* d_in, const int* in_sizes, int n_in,
                              void* d_out, int out_size) {
    const float* x      = (const float*)d_in[0];
    const int*   ei     = (const int*)d_in[1];
    const float* ea     = (const float*)d_in[2];
    const int*   eli    = (const int*)d_in[3];
    const float* rel_w  = (const float*)d_in[4];
    const float* rel_b  = (const float*)d_in[5];
    const float* root_w = (const float*)d_in[6];
    const float* bn_g   = (const float*)d_in[7];
    const float* bn_b   = (const float*)d_in[8];
    const float* w1     = (const float*)d_in[9];
    const float* b1     = (const float*)d_in[10];
    const float* w2     = (const float*)d_in[11];
    const float* b2     = (const float*)d_in[12];

    int N  = in_sizes[0] / HD;
    int E  = in_sizes[1] / 2;
    int EQ = in_sizes[3] / 2;
    int NC = in_sizes[4] / (HD * HD);

    float *hbuf, *stats;
    __nv_bfloat16 *ahi, *alo, *xhi, *xlo, *wtc, *wt1;
    int *deg, *tmp, *part, *rowptr, *cursor;
    int2 *cse;
    cudaGetSymbolAddress((void**)&hbuf,   g_h);
    cudaGetSymbolAddress((void**)&stats,  g_stats);
    cudaGetSymbolAddress((void**)&ahi,    g_agg_hi);
    cudaGetSymbolAddress((void**)&alo,    g_agg_lo);
    cudaGetSymbolAddress((void**)&xhi,    g_xhi);
    cudaGetSymbolAddress((void**)&xlo,    g_xlo);
    cudaGetSymbolAddress((void**)&deg,    g_deg);
    cudaGetSymbolAddress((void**)&tmp,    g_tmp);
    cudaGetSymbolAddress((void**)&part,   g_part);
    cudaGetSymbolAddress((void**)&rowptr, g_rowptr);
    cudaGetSymbolAddress((void**)&cursor, g_cursor);
    cudaGetSymbolAddress((void**)&cse,    g_cse);
    cudaGetSymbolAddress((void**)&wtc,    g_wtc);
    cudaGetSymbolAddress((void**)&wt1,    g_wt1);

    cudaFuncSetAttribute(conv_mma, cudaFuncAttributeMaxDynamicSharedMemorySize, CONV_SMEM);
    cudaFuncSetAttribute(mlp_mma,  cudaFuncAttributeMaxDynamicSharedMemorySize, MLP_SMEM);

    int n32 = N * 32;
    int NB = (N + 1023) / 1024;
    int gb = (N + 127) / 128;
    int mb = (EQ + 127) / 128;
    int bnHalf = (n32 + 1) / 2;
    int bnb_blk = (bnHalf + 255) / 256;

    mega_prep<<<(n32 + 255) / 256, 256>>>((const float4*)x, (uint2*)xhi, (uint2*)xlo,
                                          rel_w, root_w, w1, ei, deg, NC, n32, E);
    scan1<<<NB, 256>>>(deg, tmp, part, N);
    scan3p<<<(N + 256) / 256, 256>>>(tmp, part, rowptr, cursor, N, E, NB);
    fill_csr<<<(E + 255) / 256, 256>>>(ei, ea, cursor, cse, deg, E, N);

    for (int l = 0; l < NC; l++) {
        agg_kernel<<<(N + 7) / 8, 256>>>((const uint2*)xhi, (const uint2*)xlo,
                                         rowptr, cse,
                                         (uint2*)ahi, (uint2*)alo, stats, N);
        size_t wb = (size_t)(l * 2) * 2 * HD * HD;
        conv_mma<<<gb, 256, CONV_SMEM>>>(
            (const char*)ahi, (const char*)alo, (const char*)xhi, (const char*)xlo,
            (const char*)(wtc + wb), (const char*)(wtc + wb + HD * HD),
            (const char*)(wtc + wb + 2 * HD * HD), (const char*)(wtc + wb + 3 * HD * HD),
            rel_b + (size_t)l * HD, hbuf, stats, N);
        bn_kernel<<<bnb_blk, 256>>>((const float4*)hbuf, stats,
                                    bn_g + (size_t)l * HD, bn_b + (size_t)l * HD,
                                    (uint2*)xhi, (uint2*)xlo, N);
    }
    mlp_mma<<<mb, 256, MLP_SMEM>>>((const char*)xhi, (const char*)xlo, eli,
                                   wt1, wt1 + (size_t)HD * 2 * HD,
                                   b1, w2, b2, (float*)d_out, EQ);
}